// round 6
// baseline (speedup 1.0000x reference)
#include <cuda_runtime.h>
#include <cuda_bf16.h>
#include <math.h>

// Problem constants (fixed by reference setup_inputs):
//   n = 100000 nodes, seq_len = 4, hidden = 128, n_edges = 1.6M
#define MAX_N      100000
#define MAX_EDGES  1600000
#define HIDDEN     128
#define SEQ_STRIDE (4 * 128)   // floats per node in semantics

#define TPB        512         // threads per fused block (16 warps)
#define NPB        16          // nodes per tile
#define WT_STRIDE  130         // padded smem stride for W^T (EVEN: keeps
                               // LDS.64 8B-aligned; mod 32 == 2 -> only a
                               // 2-way bank conflict on the W read)

// Scratch (device globals; no allocations allowed).
__device__ int g_cnt[MAX_N];          // per-target edge counts (histogram)
__device__ int g_off[MAX_N + 1];      // CSR row offsets
__device__ int g_cursor[MAX_N];       // placement cursors (copy of offsets)
__device__ int g_srcs[MAX_EDGES];     // src indices sorted by tgt
__device__ int g_idx_is_64;           // 1 = int64 edge_index, 0 = int32

// ---------------------------------------------------------------------------
// f32x2 packed-FMA helpers (Blackwell fma.rn.f32x2 — 2 FMA per issue slot).
// ---------------------------------------------------------------------------
__device__ __forceinline__ void fma_f32x2(unsigned long long& d,
                                          unsigned long long a,
                                          unsigned long long b) {
    asm("fma.rn.f32x2 %0, %1, %2, %0;" : "+l"(d) : "l"(a), "l"(b));
}
__device__ __forceinline__ float hsum_f32x2(unsigned long long v) {
    float lo, hi;
    asm("mov.b64 {%0, %1}, %2;" : "=f"(lo), "=f"(hi) : "l"(v));
    return lo + hi;
}

// ---------------------------------------------------------------------------
// Probe dtype (block 0, warp 0) + zero g_cnt (whole grid, grid-stride).
// ---------------------------------------------------------------------------
__global__ void probe_memset_kernel(const long long* __restrict__ ei64,
                                    long long n, int n_nodes) {
    int tid = blockIdx.x * blockDim.x + threadIdx.x;
    for (int i = tid; i < n_nodes; i += gridDim.x * blockDim.x) g_cnt[i] = 0;

    if (blockIdx.x == 0 && threadIdx.x < 32) {
        int lane = threadIdx.x;
        int bad = 0;
        #pragma unroll
        for (int i = 0; i < 8; i++) {
            long long v = ei64[lane * 8 + i];
            if (v < 0 || v >= n) bad = 1;
        }
        unsigned m = __ballot_sync(0xFFFFFFFFu, bad);
        if (lane == 0) g_idx_is_64 = (m == 0u) ? 1 : 0;
    }
}

// ---------------------------------------------------------------------------
// Histogram of targets (paired loads: one 16B/8B load per edge).
// ---------------------------------------------------------------------------
__global__ void hist_kernel(const void* __restrict__ ei_raw, int n_edges) {
    int e = blockIdx.x * blockDim.x + threadIdx.x;
    if (e >= n_edges) return;
    int tgt;
    if (g_idx_is_64) {
        longlong2 p = __ldg((const longlong2*)ei_raw + e);
        tgt = (int)p.y;
    } else {
        int2 p = __ldg((const int2*)ei_raw + e);
        tgt = p.y;
    }
    atomicAdd(&g_cnt[tgt], 1);
}

// ---------------------------------------------------------------------------
// Single-block exclusive scan over n counts -> g_off, g_cursor.
// ---------------------------------------------------------------------------
#define SCAN_THREADS 1024
__global__ void scan_kernel(int n) {
    __shared__ int ssum[SCAN_THREADS];
    int t = threadIdx.x;
    int chunk = (n + SCAN_THREADS - 1) / SCAN_THREADS;
    int lo = t * chunk;
    int hi = min(lo + chunk, n);

    int sum = 0;
    for (int i = lo; i < hi; i++) sum += g_cnt[i];
    ssum[t] = sum;
    __syncthreads();

    for (int off = 1; off < SCAN_THREADS; off <<= 1) {
        int v = (t >= off) ? ssum[t - off] : 0;
        __syncthreads();
        ssum[t] += v;
        __syncthreads();
    }

    int run = (t == 0) ? 0 : ssum[t - 1];
    for (int i = lo; i < hi; i++) {
        int c = g_cnt[i];
        g_off[i] = run;
        g_cursor[i] = run;
        run += c;
    }
    if (t == SCAN_THREADS - 1) g_off[n] = run;
}

// ---------------------------------------------------------------------------
// Placement: bucket src indices by target (counting-sort scatter).
// ---------------------------------------------------------------------------
__global__ void place_kernel(const void* __restrict__ ei_raw, int n_edges) {
    int e = blockIdx.x * blockDim.x + threadIdx.x;
    if (e >= n_edges) return;
    int src, tgt;
    if (g_idx_is_64) {
        longlong2 p = __ldg((const longlong2*)ei_raw + e);
        src = (int)p.x; tgt = (int)p.y;
    } else {
        int2 p = __ldg((const int2*)ei_raw + e);
        src = p.x; tgt = p.y;
    }
    int pos = atomicAdd(&g_cursor[tgt], 1);
    g_srcs[pos] = src;
}

// ---------------------------------------------------------------------------
// Fused persistent kernel:
//   stage W^T into smem (once per block, stride-130 padded) ->
//   loop over 16-node tiles:
//     gather: 1 warp/node, lane-parallel CSR index load + shfl, MLP-8 float4
//             gathers into registers, mean -> s[16][128]
//     gemm:   thread (rr,j) computes rows rr,rr+4,rr+8,rr+12 of column j
//             via f32x2 packed FMA, W from smem (LDS only in hot loop)
//     exact GELU -> out
// ---------------------------------------------------------------------------
extern __shared__ float dyn_smem[];   // [128*WT_STRIDE] Wt + [16*128] s

__global__ void __launch_bounds__(TPB, 2)
agg_gemm_gelu_kernel(const float* __restrict__ sem,
                     const float* __restrict__ W,
                     float* __restrict__ out,
                     int n, int ntiles) {
    float* sWt = dyn_smem;                       // [128][WT_STRIDE] W^T padded
    float* s   = dyn_smem + HIDDEN * WT_STRIDE;  // [NPB][HIDDEN]

    // ---- Stage W transposed: sWt[col][row] = W[row][col] ----
    for (int i = threadIdx.x; i < HIDDEN * HIDDEN; i += TPB) {
        int r = i >> 7, c = i & 127;
        sWt[c * WT_STRIDE + r] = __ldg(W + i);
    }
    __syncthreads();

    const int w    = threadIdx.x >> 5;    // 0..15
    const int lane = threadIdx.x & 31;
    const int j    = threadIdx.x & 127;   // output column
    const int rr   = threadIdx.x >> 7;    // 0..3 row phase

    for (int tile = blockIdx.x; tile < ntiles; tile += gridDim.x) {
        const int base = tile * NPB;
        const int node = base + w;

        // ---- Gather phase ----
        float4 acc = make_float4(0.f, 0.f, 0.f, 0.f);
        float inv = 0.f;
        if (node < n) {
            const int beg = g_off[node];
            const int end = g_off[node + 1];
            inv = 1.0f / (float)max(end - beg, 1);

            for (int eb = beg; eb < end; eb += 32) {
                const int m = min(32, end - eb);
                int myidx = (lane < m) ? __ldg(g_srcs + eb + lane) : 0;

                for (int t = 0; t < m; t += 8) {
                    const int kk = min(8, m - t);
                    float4 v[8];
                    #pragma unroll
                    for (int k = 0; k < 8; k++) {
                        int idx = __shfl_sync(0xFFFFFFFFu, myidx, t + k);
                        if (k < kk)
                            v[k] = __ldg((const float4*)(sem + (size_t)idx * SEQ_STRIDE) + lane);
                        else
                            v[k] = make_float4(0.f, 0.f, 0.f, 0.f);
                    }
                    #pragma unroll
                    for (int k = 0; k < 8; k++) {
                        acc.x += v[k].x; acc.y += v[k].y;
                        acc.z += v[k].z; acc.w += v[k].w;
                    }
                }
            }
        }
        *(float4*)&s[w * HIDDEN + lane * 4] =
            make_float4(acc.x * inv, acc.y * inv, acc.z * inv, acc.w * inv);
        __syncthreads();

        // ---- GEMM phase: rows rr, rr+4, rr+8, rr+12; column j ----
        unsigned long long acc2[4] = {0ull, 0ull, 0ull, 0ull};
        const float* wj = sWt + j * WT_STRIDE;   // 8B-aligned (WT_STRIDE even)

        #pragma unroll 8
        for (int k = 0; k < HIDDEN; k += 2) {
            unsigned long long w2 = *(const unsigned long long*)(wj + k);
            #pragma unroll
            for (int i = 0; i < 4; i++) {
                unsigned long long s2 =
                    *(const unsigned long long*)&s[(rr + 4 * i) * HIDDEN + k];
                fma_f32x2(acc2[i], s2, w2);
            }
        }

        #pragma unroll
        for (int i = 0; i < 4; i++) {
            int row = base + rr + 4 * i;
            if (row < n) {
                float mv = hsum_f32x2(acc2[i]);
                // exact GELU: 0.5*x*(1 + erf(x/sqrt(2)))
                out[(size_t)row * HIDDEN + j] =
                    0.5f * mv * (1.0f + erff(mv * 0.70710678118654752f));
            }
        }
        __syncthreads();   // s reused next tile
    }
}

// ---------------------------------------------------------------------------
// kernel_launch: probe+memset -> hist -> scan -> place -> fused persistent.
// All async on the default stream; graph-capturable; no allocations.
// Input order (metadata): semantics, attention_masks (unused), W, edge_index.
// ---------------------------------------------------------------------------
extern "C" void kernel_launch(void* const* d_in, const int* in_sizes, int n_in,
                              void* d_out, int out_size) {
    const float* sem = (const float*)d_in[0];
    const float* W   = (const float*)d_in[2];
    const void*  ei  = d_in[3];
    float* out = (float*)d_out;

    const int n       = in_sizes[0] / SEQ_STRIDE;   // 100000
    const int n_edges = in_sizes[3] / 2;            // 1600000

    probe_memset_kernel<<<200, 512>>>((const long long*)ei, (long long)n, n);

    int eb = (n_edges + 511) / 512;
    hist_kernel<<<eb, 512>>>(ei, n_edges);
    scan_kernel<<<1, SCAN_THREADS>>>(n);
    place_kernel<<<eb, 512>>>(ei, n_edges);

    const int ntiles = (n + NPB - 1) / NPB;
    const int smem_bytes = (HIDDEN * WT_STRIDE + NPB * HIDDEN) * (int)sizeof(float);
    cudaFuncSetAttribute(agg_gemm_gelu_kernel,
                         cudaFuncAttributeMaxDynamicSharedMemorySize,
                         smem_bytes);
    agg_gemm_gelu_kernel<<<444, TPB, smem_bytes>>>(sem, W, out, n, ntiles);
}